// round 9
// baseline (speedup 1.0000x reference)
#include <cuda_runtime.h>
#include <cstdint>

#define NB      16         // batch
#define C       256        // channels
#define CH      128        // C/2 hidden / selected count
#define HW      16384      // 128*128 spatial
#define HW4     4096       // HW / 4 (float4)
#define CHUNK_B 2          // batches per chunk (32 MB of x)
#define NCHUNK  (NB / CHUNK_B)        // 8
#define CTASKS  (CHUNK_B * C)         // 512 channel-tasks per chunk

__device__ float g_z[NB * C];     // channel means
__device__ int   g_dst[NB * C];   // channel c -> output slot
__device__ int   g_flag[NB];      // per-batch "ranks ready" (set+reset in-kernel)
__device__ int   g_done[NCHUNK];  // per-chunk scatter completion counters

// ---------------------------------------------------------------------------
// Channel mean for one (n,c). Bit-identical math to the rel_err-0 kernels.
// Default-cached reads: populates L2 for the NEXT kernel's scatter of this chunk.
// ---------------------------------------------------------------------------
__device__ __forceinline__ void mean_task(const float* __restrict__ x, int nc)
{
    const float4* __restrict__ p =
        reinterpret_cast<const float4*>(x + (size_t)nc * HW);
    float s = 0.0f;
    #pragma unroll
    for (int k = 0; k < HW4 / 256; ++k) {
        float4 v = p[threadIdx.x + k * 256];
        s += (v.x + v.y) + (v.z + v.w);
    }
    #pragma unroll
    for (int o = 16; o > 0; o >>= 1)
        s += __shfl_xor_sync(0xFFFFFFFFu, s, o);

    __shared__ float red[8];
    const int lane = threadIdx.x & 31, wid = threadIdx.x >> 5;
    if (lane == 0) red[wid] = s;
    __syncthreads();
    if (threadIdx.x == 0) {
        float t = 0.0f;
        #pragma unroll
        for (int w = 0; w < 8; ++w) t += red[w];
        g_z[nc] = t * (1.0f / (float)HW);
    }
}

// ---------------------------------------------------------------------------
// MLP + sigmoid + stable rank for batch n. Means were written by the PREVIOUS
// kernel launch (cross-launch visibility is guaranteed). Sets g_flag[n].
// ---------------------------------------------------------------------------
__device__ void mlp_task(int n,
    const float* __restrict__ W1, const float* __restrict__ b1,
    const float* __restrict__ W2, const float* __restrict__ b2)
{
    const int t    = threadIdx.x;
    const int lane = t & 31;
    const int wid  = t >> 5;

    __shared__ __align__(16) float z[C];
    __shared__ __align__(16) float h[CH];
    __shared__ float sc[C];

    z[t] = __ldcg(&g_z[n * C + t]);
    __syncthreads();

    const float4* __restrict__ z4 = reinterpret_cast<const float4*>(z);

    #pragma unroll
    for (int ii = 0; ii < 16; ++ii) {
        const int i = wid * 16 + ii;
        const float4* __restrict__ w4 =
            reinterpret_cast<const float4*>(W1 + i * C);
        float4 wa = w4[lane], wb = w4[lane + 32];
        float4 za = z4[lane], zb = z4[lane + 32];
        float a = wa.x * za.x;
        a = fmaf(wa.y, za.y, a); a = fmaf(wa.z, za.z, a); a = fmaf(wa.w, za.w, a);
        a = fmaf(wb.x, zb.x, a); a = fmaf(wb.y, zb.y, a);
        a = fmaf(wb.z, zb.z, a); a = fmaf(wb.w, zb.w, a);
        #pragma unroll
        for (int o = 16; o > 0; o >>= 1)
            a += __shfl_xor_sync(0xFFFFFFFFu, a, o);
        if (lane == 0) {
            float v = a + b1[i];
            h[i] = v > 0.0f ? v : 0.0f;
        }
    }
    __syncthreads();

    const float4* __restrict__ h4 = reinterpret_cast<const float4*>(h);

    #pragma unroll
    for (int ii = 0; ii < 32; ++ii) {
        const int i = wid * 32 + ii;
        const float4* __restrict__ w4 =
            reinterpret_cast<const float4*>(W2 + i * CH);
        float4 wa = w4[lane];
        float4 ha = h4[lane];
        float a = wa.x * ha.x;
        a = fmaf(wa.y, ha.y, a); a = fmaf(wa.z, ha.z, a); a = fmaf(wa.w, ha.w, a);
        #pragma unroll
        for (int o = 16; o > 0; o >>= 1)
            a += __shfl_xor_sync(0xFFFFFFFFu, a, o);
        if (lane == 0)
            sc[i] = 1.0f / (1.0f + expf(-(a + b2[i])));
    }
    __syncthreads();

    // Stable descending rank (matches jnp.argsort(-scores))
    const float mys = sc[t];
    int rank = 0;
    #pragma unroll 8
    for (int j = 0; j < C; ++j) {
        float sj = sc[j];
        rank += (sj > mys) || (sj == mys && j < t);
    }
    g_dst[n * C + t] = rank;
    __syncthreads();
    if (t == 0) {
        __threadfence();                 // release g_dst before flag
        atomicExch(&g_flag[n], 1);
    }
}

// ---------------------------------------------------------------------------
// Scatter one channel: prefetch own channel into L2, bounded-spin on the
// batch's rank flag (set by wave-1 mlp blocks in THIS kernel), then copy.
// Linear L2-warm read, permuted streaming write. Last finisher per chunk
// resets that chunk's flags + counter (graph-replay determinism).
// ---------------------------------------------------------------------------
__device__ __forceinline__ void scatter_wait_task(
    const float* __restrict__ x, float* __restrict__ out, int b, int ck)
{
    const int n = b >> 8;
    const float4* __restrict__ src =
        reinterpret_cast<const float4*>(x + (size_t)b * HW);

    // prefetch full 64KB channel (2 x 128B per thread) while ranks settle
    const char* sp = (const char*)src + threadIdx.x * 256;
    asm volatile("prefetch.global.L2 [%0];"     :: "l"(sp));
    asm volatile("prefetch.global.L2 [%0+128];" :: "l"(sp));

    if (threadIdx.x == 0) {
        while (atomicAdd(&g_flag[n], 0) == 0) __nanosleep(64);
        __threadfence();                 // acquire g_dst
    }
    __syncthreads();

    const int slot = __ldcg(&g_dst[b]);

    size_t dst_ch;
    if (slot < CH) dst_ch = (size_t)n * CH + slot;                          // selected
    else           dst_ch = (size_t)NB * CH + (size_t)n * CH + (slot - CH); // remaining
    float4* __restrict__ dst = reinterpret_cast<float4*>(out + dst_ch * HW);

    #pragma unroll
    for (int half = 0; half < 2; ++half) {
        const int off = half * (HW4 / 2) + threadIdx.x;
        float4 r[8];
        #pragma unroll
        for (int k = 0; k < 8; ++k)
            r[k] = src[off + k * 256];
        #pragma unroll
        for (int k = 0; k < 8; ++k)
            __stcs(&dst[off + k * 256], r[k]);
    }

    __syncthreads();
    if (threadIdx.x == 0) {
        int d = atomicAdd(&g_done[ck], 1);
        if (d == CTASKS - 1) {           // last scatter block of this chunk
            #pragma unroll
            for (int i = 0; i < CHUNK_B; ++i)
                g_flag[ck * CHUNK_B + i] = 0;
            __threadfence();
            atomicExch(&g_done[ck], 0);
        }
    }
}

// ---------------------------------------------------------------------------
// Launch 1: means of chunk 0 only.
__global__ __launch_bounds__(256) void mean0_kernel(const float* __restrict__ x)
{
    mean_task(x, blockIdx.x);
}

// Launches 2..8: [mlp(ck) | mean(ck+1) | scatter(ck)] in one grid.
// mlp blocks first (wave-1, no dependencies), means next (pump DRAM),
// scatter last (L2-warm reads + writes, overlapped with means).
__global__ __launch_bounds__(256) void step_kernel(
    const float* __restrict__ x,
    const float* __restrict__ W1, const float* __restrict__ b1,
    const float* __restrict__ W2, const float* __restrict__ b2,
    float* __restrict__ out, int ck)
{
    const int bid = blockIdx.x;
    if (bid < CHUNK_B) {
        mlp_task(ck * CHUNK_B + bid, W1, b1, W2, b2);
    } else if (bid < CHUNK_B + CTASKS) {
        mean_task(x, (ck + 1) * CTASKS + (bid - CHUNK_B));
    } else {
        scatter_wait_task(x, out, ck * CTASKS + (bid - CHUNK_B - CTASKS), ck);
    }
}

// Launch 9: last chunk has no next mean — just mlp + scatter.
__global__ __launch_bounds__(256) void final_kernel(
    const float* __restrict__ x,
    const float* __restrict__ W1, const float* __restrict__ b1,
    const float* __restrict__ W2, const float* __restrict__ b2,
    float* __restrict__ out)
{
    const int bid = blockIdx.x;
    const int ck  = NCHUNK - 1;
    if (bid < CHUNK_B) {
        mlp_task(ck * CHUNK_B + bid, W1, b1, W2, b2);
    } else {
        scatter_wait_task(x, out, ck * CTASKS + (bid - CHUNK_B), ck);
    }
}

// ---------------------------------------------------------------------------
extern "C" void kernel_launch(void* const* d_in, const int* in_sizes, int n_in,
                              void* d_out, int out_size)
{
    const float* x  = (const float*)d_in[0];
    const float* W1 = (const float*)d_in[1];
    const float* b1 = (const float*)d_in[2];
    const float* W2 = (const float*)d_in[3];
    const float* b2 = (const float*)d_in[4];
    float* out = (float*)d_out;

    mean0_kernel<<<CTASKS, 256>>>(x);
    for (int ck = 0; ck < NCHUNK - 1; ++ck)
        step_kernel<<<CHUNK_B + 2 * CTASKS, 256>>>(x, W1, b1, W2, b2, out, ck);
    final_kernel<<<CHUNK_B + CTASKS, 256>>>(x, W1, b1, W2, b2, out);
}